// round 16
// baseline (speedup 1.0000x reference)
#include <cuda_runtime.h>

#define T 4096
#define H 4096
#define K 8
#define E 64
#define TK (T*K)            // 32768 slots
#define SORTB 64            // sort blocks (blocks 0..63), 512 slots each

// Scratch (no cudaMalloc allowed)
__device__ int g_rank[TK];            // stable rank within (sortblock, expert)
__device__ int g_blockcount[SORTB*E];
__device__ int g_blockbase[SORTB*E];
__device__ int g_expertbase[E];
__device__ unsigned g_arrive;         // monotonic sort-arrival counter (64/launch)

// ---------------------------------------------------------------------------
// Kernel 1: sort + combined. No inter-block synchronization needed — the two
// roles are independent, and k2 (which consumes the sort) is ordered by the
// stream. Blocks [0,64): counting sort; last-arriving block (atomic ticket)
// does cross-block + cross-expert scans and emits tokens_per_expert.
// Blocks [64,4160): combined-only — read the 16KB x row, write the weighted
// row with __stcs (streaming: keeps x resident in L2 for k2's re-read).
// ---------------------------------------------------------------------------
__global__ void __launch_bounds__(256) k1_sort_comb(const float4* __restrict__ x4,
                                                    const float*  __restrict__ wts,
                                                    const int*    __restrict__ idx,
                                                    float4* __restrict__ comb4,
                                                    float*  __restrict__ tpe) {
    const int tid = threadIdx.x;

    if (blockIdx.x < SORTB) {
        // ================= SORT ROLE =================
        __shared__ int whist[16 * E];  // warps 0-7: chunk0, warps 8-15: chunk1
        __shared__ int s_last;
        const int b    = blockIdx.x;
        const int w    = tid >> 5;
        const int lane = tid & 31;

        #pragma unroll
        for (int i = 0; i < 4; i++) whist[tid + i * 256] = 0;
        __syncthreads();

        const int s0 = b * 512 + tid;
        const int s1 = s0 + 256;
        const int e0 = __ldg(&idx[s0]);
        const int e1 = __ldg(&idx[s1]);

        const unsigned m0 = __match_any_sync(0xffffffffu, e0);
        const int riw0 = __popc(m0 & ((1u << lane) - 1u));
        if ((__ffs(m0) - 1) == lane) whist[w * E + e0] = __popc(m0);
        const unsigned m1 = __match_any_sync(0xffffffffu, e1);
        const int riw1 = __popc(m1 & ((1u << lane) - 1u));
        if ((__ffs(m1) - 1) == lane) whist[(w + 8) * E + e1] = __popc(m1);
        __syncthreads();

        if (tid < E) {                 // scan 16 warp counts (chunk0 first = stable)
            int run = 0;
            #pragma unroll
            for (int ww = 0; ww < 16; ww++) {
                const int c = whist[ww * E + tid];
                whist[ww * E + tid] = run;
                run += c;
            }
            g_blockcount[b * E + tid] = run;
        }
        __syncthreads();

        g_rank[s0] = whist[w * E + e0] + riw0;
        g_rank[s1] = whist[(w + 8) * E + e1] + riw1;

        __threadfence();
        if (tid == 0) {
            const unsigned ticket = atomicAdd(&g_arrive, 1u);
            s_last = ((ticket & (SORTB - 1)) == (SORTB - 1));
        }
        __syncthreads();

        if (s_last) {
            __threadfence();
            __shared__ int tot[E];
            __shared__ int base[E];
            if (tid < E) {
                int run = 0;
                #pragma unroll
                for (int bb = 0; bb < SORTB; bb++) {
                    const int c = g_blockcount[bb * E + tid];
                    g_blockbase[bb * E + tid] = run;
                    run += c;
                }
                tot[tid] = run;
            }
            __syncthreads();
            if (tid == 0) {
                int acc = 0;
                #pragma unroll
                for (int i = 0; i < E; i++) { base[i] = acc; acc += tot[i]; }
            }
            __syncthreads();
            if (tid < E) {
                g_expertbase[tid] = base[tid];
                if (tpe) tpe[tid] = (float)tot[tid];
            }
        }
    } else if (comb4) {
        // ================= COMBINED ROLE =================
        const int t = blockIdx.x - SORTB;
        const int ROW4 = H / 4;        // 1024 float4 per row

        float ws = 0.f;
        #pragma unroll
        for (int k = 0; k < K; k++) ws += __ldg(&wts[t * K + k]);

        #pragma unroll
        for (int i = 0; i < 4; i++) {
            float4 v = __ldg(&x4[(size_t)t * ROW4 + tid + i * 256]);
            float4 o = make_float4(v.x * ws, v.y * ws, v.z * ws, v.w * ws);
            __stcs(&comb4[(size_t)t * ROW4 + tid + i * 256], o);
        }
    }
}

// ---------------------------------------------------------------------------
// Kernel 2: dispatched-only. One block per token. x rows were streamed
// through L2 by k1 moments ago — the re-read is largely L2 hits; the 512MB
// scatter is pure streaming writes. No sync, no polls, no stalls anywhere.
// ---------------------------------------------------------------------------
__global__ void __launch_bounds__(256) k2_dispatch(const float4* __restrict__ x4,
                                                   const int*    __restrict__ idx,
                                                   float4* __restrict__ disp4) {
    const int t   = blockIdx.x;
    const int tid = threadIdx.x;
    const int ROW4 = H / 4;            // 1024 float4 per row

    float4 v[4];
    #pragma unroll
    for (int i = 0; i < 4; i++)
        v[i] = __ldg(&x4[(size_t)t * ROW4 + tid + i * 256]);

    int dst[K];
    #pragma unroll
    for (int k = 0; k < K; k++) {
        const int s  = t * K + k;
        const int bb = s >> 9;         // 512 slots per sort block
        const int e  = __ldg(&idx[s]);
        dst[k] = __ldg(&g_expertbase[e]) + __ldg(&g_blockbase[bb * E + e])
               + __ldg(&g_rank[s]);
    }

    #pragma unroll
    for (int k = 0; k < K; k++) {
        const size_t basep = (size_t)dst[k] * ROW4;
        #pragma unroll
        for (int i = 0; i < 4; i++)
            __stcs(&disp4[basep + tid + i * 256], v[i]);
    }
}

// ---------------------------------------------------------------------------
extern "C" void kernel_launch(void* const* d_in, const int* in_sizes, int n_in,
                              void* d_out, int out_size) {
    const float* x   = (const float*)d_in[0];
    const int*   idx = (const int*)  d_in[1];
    const float* w   = (const float*)d_in[2];
    float* out = (float*)d_out;

    const long long TH  = (long long)T * H;          // 16,777,216
    const long long TKH = (long long)TK * H;         // 134,217,728
    const long long os  = (long long)out_size;

    float* comb = nullptr;
    float* disp = nullptr;
    float* tpe  = nullptr;

    if (os >= TH + TKH) {
        comb = out;
        disp = out + TH;
        if (os >= TH + TKH + E) tpe = out + TH + TKH;
    } else if (os == TKH) {
        disp = out;                                  // dispatched-only layout
    } else {
        comb = out;                                  // combined-only layout
    }

    // k1: sort + combined. If there is no combined output, the token blocks
    // early-out and k1 is just the (cheap) sort.
    k1_sort_comb<<<SORTB + T, 256>>>((const float4*)x, w, idx, (float4*)comb, tpe);

    // k2: dispatched scatter (ordered after k1 by the stream).
    if (disp) {
        k2_dispatch<<<T, 256>>>((const float4*)x, idx, (float4*)disp);
    }
}

// round 17
// speedup vs baseline: 1.0422x; 1.0422x over previous
#include <cuda_runtime.h>

#define T 4096
#define H 4096
#define K 8
#define E 64
#define TK (T*K)            // 32768 slots
#define SORTB 64            // sort blocks (blocks 0..63), 512 slots each
#define NTOKB 888           // persistent token blocks (6/SM x 148 SMs)
#define NTOT (SORTB + NTOKB)
#define NFLAG 32            // flag replicas, one per 128B line

// Scratch (no cudaMalloc allowed)
__device__ int g_rank[TK];            // stable rank within (sortblock, expert)
__device__ int g_blockcount[SORTB*E];
__device__ int g_blockbase[SORTB*E];
__device__ int g_expertbase[E];
__device__ unsigned g_arrive;         // monotonic sort-arrival counter (64/launch)
__device__ unsigned g_tok;            // monotonic token-entry counter (888/launch)
__device__ unsigned g_flags[NFLAG * 32];  // epoch flags, replica i at [i*32]

// ---------------------------------------------------------------------------
// One fused kernel, persistent token blocks with DEFERRAL instead of stalls.
// Blocks [0,64): counting sort (R13 version); last-arriving block scans and
// publishes epoch+1 to all 32 flag replicas.
// Blocks [64,952): each owns tokens t = j, j+888, ... For each token: row
// load -> combined write -> flag CHECK (no wait). If unset, the row is
// stashed in smem and dispatched on a later iteration when the flag is up —
// no stall, no re-read. Waiting is a rare fallback (2 consecutive unset
// checks or pending at loop end).
// ---------------------------------------------------------------------------
__global__ void __launch_bounds__(256) k_fused(const float4* __restrict__ x4,
                                               const float*  __restrict__ wts,
                                               const int*    __restrict__ idx,
                                               float4* __restrict__ comb4,
                                               float4* __restrict__ disp4,
                                               float*  __restrict__ tpe) {
    const int tid = threadIdx.x;

    if (blockIdx.x < SORTB) {
        // ================= SORT ROLE =================
        __shared__ int whist[16 * E];  // warps 0-7: chunk0, warps 8-15: chunk1
        __shared__ int s_last;
        __shared__ unsigned s_epoch;
        const int b    = blockIdx.x;
        const int w    = tid >> 5;
        const int lane = tid & 31;

        #pragma unroll
        for (int i = 0; i < 4; i++) whist[tid + i * 256] = 0;
        __syncthreads();

        const int s0 = b * 512 + tid;
        const int s1 = s0 + 256;
        const int e0 = __ldg(&idx[s0]);
        const int e1 = __ldg(&idx[s1]);

        const unsigned m0 = __match_any_sync(0xffffffffu, e0);
        const int riw0 = __popc(m0 & ((1u << lane) - 1u));
        if ((__ffs(m0) - 1) == lane) whist[w * E + e0] = __popc(m0);
        const unsigned m1 = __match_any_sync(0xffffffffu, e1);
        const int riw1 = __popc(m1 & ((1u << lane) - 1u));
        if ((__ffs(m1) - 1) == lane) whist[(w + 8) * E + e1] = __popc(m1);
        __syncthreads();

        if (tid < E) {                 // scan 16 warp counts (chunk0 first = stable)
            int run = 0;
            #pragma unroll
            for (int ww = 0; ww < 16; ww++) {
                const int c = whist[ww * E + tid];
                whist[ww * E + tid] = run;
                run += c;
            }
            g_blockcount[b * E + tid] = run;
        }
        __syncthreads();

        g_rank[s0] = whist[w * E + e0] + riw0;
        g_rank[s1] = whist[(w + 8) * E + e1] + riw1;

        __threadfence();
        if (tid == 0) {
            const unsigned ticket = atomicAdd(&g_arrive, 1u);
            s_last  = ((ticket & (SORTB - 1)) == (SORTB - 1));
            s_epoch = ticket / SORTB;
        }
        __syncthreads();

        if (s_last) {
            __threadfence();
            __shared__ int tot[E];
            __shared__ int base[E];
            if (tid < E) {
                int run = 0;
                #pragma unroll
                for (int bb = 0; bb < SORTB; bb++) {
                    const int c = g_blockcount[bb * E + tid];
                    g_blockbase[bb * E + tid] = run;
                    run += c;
                }
                tot[tid] = run;
            }
            __syncthreads();
            if (tid == 0) {
                int acc = 0;
                #pragma unroll
                for (int i = 0; i < E; i++) { base[i] = acc; acc += tot[i]; }
            }
            __syncthreads();
            if (tid < E) {
                g_expertbase[tid] = base[tid];
                if (tpe) tpe[tid] = (float)tot[tid];
            }
            __threadfence();
            if (tid < NFLAG) atomicMax(&g_flags[tid * 32], s_epoch + 1u);
        }
    } else {
        // ================= TOKEN ROLE (persistent, deferral) =================
        const int j = blockIdx.x - SORTB;
        const int ROW4 = H / 4;        // 1024 float4 per row
        __shared__ float4 stash[1024]; // 16 KB pending-row buffer
        __shared__ unsigned s_ep;
        __shared__ unsigned s_ok;

        if (tid == 0) s_ep = atomicAdd(&g_tok, 1u) / (unsigned)NTOKB;
        __syncthreads();
        const unsigned my_epoch = s_ep;
        const int fi = (blockIdx.x & (NFLAG - 1)) * 32;

        int  pend   = -1;    // uniform across threads (block-uniform branches)
        bool fenced = false;

        for (int t = j; t < T; t += NTOKB) {
            float4 v[4];
            #pragma unroll
            for (int i = 0; i < 4; i++)
                v[i] = __ldg(&x4[(size_t)t * ROW4 + tid + i * 256]);

            float ws = 0.f;
            #pragma unroll
            for (int k = 0; k < K; k++) ws += __ldg(&wts[t * K + k]);

            if (comb4) {
                #pragma unroll
                for (int i = 0; i < 4; i++) {
                    float4 o = make_float4(v[i].x * ws, v[i].y * ws, v[i].z * ws, v[i].w * ws);
                    __stcs(&comb4[(size_t)t * ROW4 + tid + i * 256], o);
                }
            }

            if (disp4) {
                // Non-blocking flag check.
                if (tid == 0) s_ok = (*((volatile unsigned*)&g_flags[fi]) > my_epoch);
                __syncthreads();
                const int ok = (int)s_ok;
                __syncthreads();        // reads done before next iteration's write

                if (ok || pend >= 0) {
                    if (!ok) {          // rare: 2nd consecutive unset -> must wait
                        if (tid == 0) {
                            while (*((volatile unsigned*)&g_flags[fi]) <= my_epoch)
                                __nanosleep(64);
                        }
                        __syncthreads();
                    }
                    if (!fenced) { __threadfence(); fenced = true; }

                    // Dispatch current token from registers.
                    #pragma unroll
                    for (int k = 0; k < K; k++) {
                        const int s  = t * K + k;
                        const int bb = s >> 9;
                        const int e  = __ldg(&idx[s]);
                        const int d  = g_expertbase[e] + g_blockbase[bb * E + e] + g_rank[s];
                        const size_t basep = (size_t)d * ROW4;
                        #pragma unroll
                        for (int i = 0; i < 4; i++)
                            __stcs(&disp4[basep + tid + i * 256], v[i]);
                    }
                    // Drain pending token from smem (per-thread own slots).
                    if (pend >= 0) {
                        float4 p[4];
                        #pragma unroll
                        for (int i = 0; i < 4; i++) p[i] = stash[tid + i * 256];
                        #pragma unroll
                        for (int k = 0; k < K; k++) {
                            const int s  = pend * K + k;
                            const int bb = s >> 9;
                            const int e  = __ldg(&idx[s]);
                            const int d  = g_expertbase[e] + g_blockbase[bb * E + e] + g_rank[s];
                            const size_t basep = (size_t)d * ROW4;
                            #pragma unroll
                            for (int i = 0; i < 4; i++)
                                __stcs(&disp4[basep + tid + i * 256], p[i]);
                        }
                        pend = -1;
                    }
                } else {
                    // Defer: stash the row, dispatch later. No stall.
                    #pragma unroll
                    for (int i = 0; i < 4; i++) stash[tid + i * 256] = v[i];
                    pend = t;
                }
            }
        }

        // Drain a pending token left at loop end (rare).
        if (disp4 && pend >= 0) {
            if (tid == 0) {
                while (*((volatile unsigned*)&g_flags[fi]) <= my_epoch) __nanosleep(64);
            }
            __syncthreads();
            if (!fenced) { __threadfence(); fenced = true; }
            float4 p[4];
            #pragma unroll
            for (int i = 0; i < 4; i++) p[i] = stash[tid + i * 256];
            #pragma unroll
            for (int k = 0; k < K; k++) {
                const int s  = pend * K + k;
                const int bb = s >> 9;
                const int e  = __ldg(&idx[s]);
                const int d  = g_expertbase[e] + g_blockbase[bb * E + e] + g_rank[s];
                const size_t basep = (size_t)d * ROW4;
                #pragma unroll
                for (int i = 0; i < 4; i++)
                    __stcs(&disp4[basep + tid + i * 256], p[i]);
            }
        }
    }
    // No epilogue: epoch flags are monotonic, nothing to reset.
}

// ---------------------------------------------------------------------------
extern "C" void kernel_launch(void* const* d_in, const int* in_sizes, int n_in,
                              void* d_out, int out_size) {
    const float* x   = (const float*)d_in[0];
    const int*   idx = (const int*)  d_in[1];
    const float* w   = (const float*)d_in[2];
    float* out = (float*)d_out;

    const long long TH  = (long long)T * H;          // 16,777,216
    const long long TKH = (long long)TK * H;         // 134,217,728
    const long long os  = (long long)out_size;

    float* comb = nullptr;
    float* disp = nullptr;
    float* tpe  = nullptr;

    if (os >= TH + TKH) {
        comb = out;
        disp = out + TH;
        if (os >= TH + TKH + E) tpe = out + TH + TKH;
    } else if (os == TKH) {
        disp = out;                                  // dispatched-only layout
    } else {
        comb = out;                                  // combined-only layout
    }

    k_fused<<<NTOT, 256>>>((const float4*)x, w, idx,
                           (float4*)comb, (float4*)disp, tpe);
}